// round 14
// baseline (speedup 1.0000x reference)
#include <cuda_runtime.h>
#include <cuda_fp16.h>
#include <cuda_bf16.h>

#define NN 50000
#define EE 800000
#define HH 8
#define HC 128
#define NEG 0.2f
#define FULL 0xffffffffu

#define SCAN_T 1024
#define NB ((NN + SCAN_T - 1) / SCAN_T)   // 49

// Scratch (device globals; no cudaMalloc anywhere)
__device__ __nv_bfloat16 g_xs[NN * 256];   // [Xhi | Xlo] per row (bf16, gat GEMM)
__device__ __half        g_xh[NN * 128];   // X fp16 (skip GEMM)
__device__ __nv_bfloat16 g_wc[128 * 384];  // gat W^T: row n, k: [Whi | Wlo | Whi]
__device__ __half        g_wh[128 * 128];  // skip W^T fp16
__device__ __half2 g_hh[NN * 64];          // h  (fp16 messages)
__device__ __half2 g_sk[NN * 64];          // skip (fp16)
__device__ float   g_asrc[NN * HH];
__device__ float   g_adst[NN * HH];
__device__ int     g_cnt[NN];              // zero at run start (re-zeroed each run)
__device__ int     g_rowstart[NN + 1];
__device__ int     g_cursor[NN];
__device__ int     g_part[NB];             // scan partials+flag; zeroed in k_hist
__device__ int     g_csr[EE];

// ---------------------------------------------------------------------------
// Merged prep: X hi/lo split (bf16) + X fp16 + transposed weights (bf16 gat / fp16 skip).
#define XBLK ((NN * 32 + 255) / 256)
#define WBLK 96                            // 256*96 threads / 256

__global__ void k_prep(const float* __restrict__ X,
                       const float* __restrict__ Wg,
                       const float* __restrict__ Ws) {
    if (blockIdx.x < XBLK) {
        int t = blockIdx.x * 256 + threadIdx.x;
        int n = t >> 5, c4 = (t & 31) * 4;
        if (n >= NN) return;
        float4 v = *(const float4*)&X[n * 128 + c4];
        __nv_bfloat16 h0 = __float2bfloat16_rn(v.x);
        __nv_bfloat16 h1 = __float2bfloat16_rn(v.y);
        __nv_bfloat16 h2 = __float2bfloat16_rn(v.z);
        __nv_bfloat16 h3 = __float2bfloat16_rn(v.w);
        __nv_bfloat16 l0 = __float2bfloat16_rn(v.x - __bfloat162float(h0));
        __nv_bfloat16 l1 = __float2bfloat16_rn(v.y - __bfloat162float(h1));
        __nv_bfloat16 l2 = __float2bfloat16_rn(v.z - __bfloat162float(h2));
        __nv_bfloat16 l3 = __float2bfloat16_rn(v.w - __bfloat162float(h3));
        __nv_bfloat16 hi4[4] = {h0, h1, h2, h3};
        __nv_bfloat16 lo4[4] = {l0, l1, l2, l3};
        long base = (long)n * 256;
        *(uint2*)&g_xs[base + c4]       = *(uint2*)hi4;
        *(uint2*)&g_xs[base + 128 + c4] = *(uint2*)lo4;
        __half2 f01 = __floats2half2_rn(v.x, v.y);
        __half2 f23 = __floats2half2_rn(v.z, v.w);
        uint2 uf;
        uf.x = *(unsigned*)&f01; uf.y = *(unsigned*)&f23;
        *(uint2*)&g_xh[(long)n * 128 + c4] = uf;
    } else {
        int t = (blockIdx.x - XBLK) * 256 + threadIdx.x;   // 256*96 groups of 4
        if (t >= 256 * 96) return;
        int n = t / 96, kq = t % 96;
        int k0 = kq * 4;
        if (n < 128) {
            __nv_bfloat16 out4[4];
#pragma unroll
            for (int j = 0; j < 4; j++) {
                int k = k0 + j;
                int kk = k & 127;
                float w = Wg[kk * 128 + n];
                __nv_bfloat16 hi = __float2bfloat16_rn(w);
                out4[j] = (k >= 128 && k < 256)
                    ? __float2bfloat16_rn(w - __bfloat162float(hi)) : hi;
            }
            *(uint2*)&g_wc[n * 384 + k0] = *(uint2*)out4;
        } else if (k0 < 128) {
            int nn = n - 128;
            __half out4[4];
#pragma unroll
            for (int j = 0; j < 4; j++)
                out4[j] = __float2half_rn(Ws[(k0 + j) * 128 + nn]);
            *(uint2*)&g_wh[nn * 128 + k0] = *(uint2*)out4;
        }
    }
}

// ---------------------------------------------------------------------------
// Shared tensor-core GEMM plumbing.
#define KCH 32
#define LDA 40
#define ABUF (128 * LDA)
#define SMEM_MM (6 * ABUF * 2)           // 61440 bytes

__device__ __forceinline__ void ldsm_x4(unsigned& r0, unsigned& r1,
                                        unsigned& r2, unsigned& r3, unsigned addr) {
    asm volatile("ldmatrix.sync.aligned.m8n8.x4.shared.b16 {%0,%1,%2,%3}, [%4];"
                 : "=r"(r0), "=r"(r1), "=r"(r2), "=r"(r3) : "r"(addr));
}

// ---------------------------------------------------------------------------
// GAT GEMM (bf16 3-pass, virtual K=384), h + attention dots. Grid: 391 blocks.
#define NCH 12

__global__ void __launch_bounds__(256)
k_mm(const float* __restrict__ att_s, const float* __restrict__ att_d) {
    extern __shared__ __nv_bfloat16 smem[];
    int tid = threadIdx.x;
    int wid = tid >> 5, lane = tid & 31;
    int g = lane >> 2, t = lane & 3;
    int m0 = blockIdx.x * 128;
    int wrow = (wid >> 1) * 32, wcol = (wid & 1) * 64;

    unsigned s_base = (unsigned)__cvta_generic_to_shared(&smem[0]);
    const unsigned stage_bytes = ABUF * 2;

    int r0i = tid >> 2, c8 = (tid & 3) * 8;
    int r1i = (tid + 256) >> 2;
    int gmA0 = m0 + r0i, gmA1 = m0 + r1i;
    const __nv_bfloat16* wrow0 = &g_wc[r0i * 384 + c8];
    const __nv_bfloat16* wrow1 = &g_wc[r1i * 384 + c8];
    const __nv_bfloat16* xrow0 = &g_xs[(long)min(gmA0, NN - 1) * 256 + c8];
    const __nv_bfloat16* xrow1 = &g_xs[(long)min(gmA1, NN - 1) * 256 + c8];
    int szA0 = (gmA0 < NN) ? 16 : 0;
    int szA1 = (gmA1 < NN) ? 16 : 0;
    unsigned dA0 = s_base + (r0i * LDA + c8) * 2;
    unsigned dA1 = s_base + (r1i * LDA + c8) * 2;
    unsigned dB0 = s_base + 3 * stage_bytes + (r0i * LDA + c8) * 2;
    unsigned dB1 = s_base + 3 * stage_bytes + (r1i * LDA + c8) * 2;

#define PREFETCH(ch) do {                                                     \
        if ((ch) < NCH) {                                                     \
            int _ach = ((ch) < 4) ? (ch) : (ch) - 4;                          \
            int _ka = _ach * KCH, _kb = (ch) * KCH;                           \
            unsigned _o = ((ch) % 3) * stage_bytes;                           \
            asm volatile("cp.async.ca.shared.global [%0], [%1], 16, %2;"      \
                         :: "r"(dA0 + _o), "l"(xrow0 + _ka), "r"(szA0));      \
            asm volatile("cp.async.ca.shared.global [%0], [%1], 16, %2;"      \
                         :: "r"(dA1 + _o), "l"(xrow1 + _ka), "r"(szA1));      \
            asm volatile("cp.async.ca.shared.global [%0], [%1], 16;"          \
                         :: "r"(dB0 + _o), "l"(wrow0 + _kb));                 \
            asm volatile("cp.async.ca.shared.global [%0], [%1], 16;"          \
                         :: "r"(dB1 + _o), "l"(wrow1 + _kb));                 \
        }                                                                     \
        asm volatile("cp.async.commit_group;");                               \
    } while (0)

    float d[2][8][4];
#pragma unroll
    for (int mi = 0; mi < 2; mi++)
#pragma unroll
        for (int ni = 0; ni < 8; ni++)
#pragma unroll
            for (int j = 0; j < 4; j++) d[mi][ni][j] = 0.f;

    int a_row = (lane & 15), a_kof = (lane >> 4) * 8;
    int b_row = (lane & 7) + ((lane >> 4) << 3), b_kof = ((lane >> 3) & 1) * 8;

    PREFETCH(0);
    PREFETCH(1);

    for (int c = 0; c < NCH; c++) {
        asm volatile("cp.async.wait_group 1;");
        __syncthreads();
        PREFETCH(c + 2);
        unsigned abuf = s_base + (c % 3) * stage_bytes;
        unsigned bbuf = s_base + (3 + c % 3) * stage_bytes;
#pragma unroll
        for (int kk = 0; kk < KCH; kk += 16) {
            unsigned a[2][4], b[8][2];
#pragma unroll
            for (int mi = 0; mi < 2; mi++) {
                int rb = wrow + 16 * mi;
                unsigned ad = abuf + ((rb + a_row) * LDA + kk + a_kof) * 2;
                ldsm_x4(a[mi][0], a[mi][1], a[mi][2], a[mi][3], ad);
            }
#pragma unroll
            for (int bi = 0; bi < 4; bi++) {
                int nb = wcol + 16 * bi + b_row;
                unsigned bd = bbuf + (nb * LDA + kk + b_kof) * 2;
                ldsm_x4(b[2 * bi][0], b[2 * bi][1], b[2 * bi + 1][0], b[2 * bi + 1][1], bd);
            }
#pragma unroll
            for (int mi = 0; mi < 2; mi++)
#pragma unroll
                for (int ni = 0; ni < 8; ni++) {
                    asm volatile(
                        "mma.sync.aligned.m16n8k16.row.col.f32.bf16.bf16.f32 "
                        "{%0,%1,%2,%3}, {%4,%5,%6,%7}, {%8,%9}, {%0,%1,%2,%3};\n"
                        : "+f"(d[mi][ni][0]), "+f"(d[mi][ni][1]),
                          "+f"(d[mi][ni][2]), "+f"(d[mi][ni][3])
                        : "r"(a[mi][0]), "r"(a[mi][1]), "r"(a[mi][2]), "r"(a[mi][3]),
                          "r"(b[ni][0]), "r"(b[ni][1]));
                }
        }
    }

#pragma unroll
    for (int mi = 0; mi < 2; mi++) {
        int r0 = m0 + wrow + 16 * mi + g;
        int r1 = r0 + 8;
#pragma unroll
        for (int ni = 0; ni < 8; ni++) {
            int pidx = wcol / 2 + 4 * ni + t;
            if (r0 < NN) g_hh[r0 * 64 + pidx] = __floats2half2_rn(d[mi][ni][0], d[mi][ni][1]);
            if (r1 < NN) g_hh[r1 * 64 + pidx] = __floats2half2_rn(d[mi][ni][2], d[mi][ni][3]);
        }
#pragma unroll
        for (int lh = 0; lh < 4; lh++) {
            float ps0 = 0.f, pd0 = 0.f, ps1 = 0.f, pd1 = 0.f;
#pragma unroll
            for (int j = 0; j < 2; j++) {
                int ni = 2 * lh + j;
                int c0 = wcol + 8 * ni + 2 * t;
                float as0 = att_s[c0], as1 = att_s[c0 + 1];
                float ad0 = att_d[c0], ad1 = att_d[c0 + 1];
                ps0 += d[mi][ni][0] * as0 + d[mi][ni][1] * as1;
                pd0 += d[mi][ni][0] * ad0 + d[mi][ni][1] * ad1;
                ps1 += d[mi][ni][2] * as0 + d[mi][ni][3] * as1;
                pd1 += d[mi][ni][2] * ad0 + d[mi][ni][3] * ad1;
            }
            ps0 += __shfl_xor_sync(FULL, ps0, 1); ps0 += __shfl_xor_sync(FULL, ps0, 2);
            pd0 += __shfl_xor_sync(FULL, pd0, 1); pd0 += __shfl_xor_sync(FULL, pd0, 2);
            ps1 += __shfl_xor_sync(FULL, ps1, 1); ps1 += __shfl_xor_sync(FULL, ps1, 2);
            pd1 += __shfl_xor_sync(FULL, pd1, 1); pd1 += __shfl_xor_sync(FULL, pd1, 2);
            int head = wcol / 16 + lh;
            if (t == 0) {
                if (r0 < NN) { g_asrc[r0 * HH + head] = ps0; g_adst[r0 * HH + head] = pd0; }
                if (r1 < NN) { g_asrc[r1 * HH + head] = ps1; g_adst[r1 * HH + head] = pd1; }
            }
        }
    }
}

// ---------------------------------------------------------------------------
// SKIP GEMM: single fp16 pass, K=128 (4 chunks).
#define NCHS 4

__global__ void __launch_bounds__(256)
k_mmskip() {
    extern __shared__ __nv_bfloat16 smem[];
    int tid = threadIdx.x;
    int wid = tid >> 5, lane = tid & 31;
    int g = lane >> 2, t = lane & 3;
    int m0 = blockIdx.x * 128;
    int wrow = (wid >> 1) * 32, wcol = (wid & 1) * 64;

    unsigned s_base = (unsigned)__cvta_generic_to_shared(&smem[0]);
    const unsigned stage_bytes = ABUF * 2;

    int r0i = tid >> 2, c8 = (tid & 3) * 8;
    int r1i = (tid + 256) >> 2;
    int gmA0 = m0 + r0i, gmA1 = m0 + r1i;
    const __half* wrow0 = &g_wh[r0i * 128 + c8];
    const __half* wrow1 = &g_wh[r1i * 128 + c8];
    const __half* xrow0 = &g_xh[(long)min(gmA0, NN - 1) * 128 + c8];
    const __half* xrow1 = &g_xh[(long)min(gmA1, NN - 1) * 128 + c8];
    int szA0 = (gmA0 < NN) ? 16 : 0;
    int szA1 = (gmA1 < NN) ? 16 : 0;
    unsigned dA0 = s_base + (r0i * LDA + c8) * 2;
    unsigned dA1 = s_base + (r1i * LDA + c8) * 2;
    unsigned dB0 = s_base + 3 * stage_bytes + (r0i * LDA + c8) * 2;
    unsigned dB1 = s_base + 3 * stage_bytes + (r1i * LDA + c8) * 2;

#define PREFETCH_S(ch) do {                                                   \
        if ((ch) < NCHS) {                                                    \
            int _kb = (ch) * KCH;                                             \
            unsigned _o = ((ch) % 3) * stage_bytes;                           \
            asm volatile("cp.async.ca.shared.global [%0], [%1], 16, %2;"      \
                         :: "r"(dA0 + _o), "l"(xrow0 + _kb), "r"(szA0));      \
            asm volatile("cp.async.ca.shared.global [%0], [%1], 16, %2;"      \
                         :: "r"(dA1 + _o), "l"(xrow1 + _kb), "r"(szA1));      \
            asm volatile("cp.async.ca.shared.global [%0], [%1], 16;"          \
                         :: "r"(dB0 + _o), "l"(wrow0 + _kb));                 \
            asm volatile("cp.async.ca.shared.global [%0], [%1], 16;"          \
                         :: "r"(dB1 + _o), "l"(wrow1 + _kb));                 \
        }                                                                     \
        asm volatile("cp.async.commit_group;");                               \
    } while (0)

    float d[2][8][4];
#pragma unroll
    for (int mi = 0; mi < 2; mi++)
#pragma unroll
        for (int ni = 0; ni < 8; ni++)
#pragma unroll
            for (int j = 0; j < 4; j++) d[mi][ni][j] = 0.f;

    int a_row = (lane & 15), a_kof = (lane >> 4) * 8;
    int b_row = (lane & 7) + ((lane >> 4) << 3), b_kof = ((lane >> 3) & 1) * 8;

    PREFETCH_S(0);
    PREFETCH_S(1);

    for (int c = 0; c < NCHS; c++) {
        asm volatile("cp.async.wait_group 1;");
        __syncthreads();
        PREFETCH_S(c + 2);
        unsigned abuf = s_base + (c % 3) * stage_bytes;
        unsigned bbuf = s_base + (3 + c % 3) * stage_bytes;
#pragma unroll
        for (int kk = 0; kk < KCH; kk += 16) {
            unsigned a[2][4], b[8][2];
#pragma unroll
            for (int mi = 0; mi < 2; mi++) {
                int rb = wrow + 16 * mi;
                unsigned ad = abuf + ((rb + a_row) * LDA + kk + a_kof) * 2;
                ldsm_x4(a[mi][0], a[mi][1], a[mi][2], a[mi][3], ad);
            }
#pragma unroll
            for (int bi = 0; bi < 4; bi++) {
                int nb = wcol + 16 * bi + b_row;
                unsigned bd = bbuf + (nb * LDA + kk + b_kof) * 2;
                ldsm_x4(b[2 * bi][0], b[2 * bi][1], b[2 * bi + 1][0], b[2 * bi + 1][1], bd);
            }
#pragma unroll
            for (int mi = 0; mi < 2; mi++)
#pragma unroll
                for (int ni = 0; ni < 8; ni++) {
                    asm volatile(
                        "mma.sync.aligned.m16n8k16.row.col.f32.f16.f16.f32 "
                        "{%0,%1,%2,%3}, {%4,%5,%6,%7}, {%8,%9}, {%0,%1,%2,%3};\n"
                        : "+f"(d[mi][ni][0]), "+f"(d[mi][ni][1]),
                          "+f"(d[mi][ni][2]), "+f"(d[mi][ni][3])
                        : "r"(a[mi][0]), "r"(a[mi][1]), "r"(a[mi][2]), "r"(a[mi][3]),
                          "r"(b[ni][0]), "r"(b[ni][1]));
                }
        }
    }

#pragma unroll
    for (int mi = 0; mi < 2; mi++) {
        int r0 = m0 + wrow + 16 * mi + g;
        int r1 = r0 + 8;
#pragma unroll
        for (int ni = 0; ni < 8; ni++) {
            int pidx = wcol / 2 + 4 * ni + t;
            if (r0 < NN) g_sk[r0 * 64 + pidx] = __floats2half2_rn(d[mi][ni][0], d[mi][ni][1]);
            if (r1 < NN) g_sk[r1 * 64 + pidx] = __floats2half2_rn(d[mi][ni][2], d[mi][ni][3]);
        }
    }
}

// ---------------------------------------------------------------------------
// CSR build: vectorized histogram (4 edges/thread) + g_part flag-zeroing.
__global__ void k_hist(const int* __restrict__ ei) {
    if (blockIdx.x == 0 && threadIdx.x < NB) g_part[threadIdx.x] = 0;
    int t = blockIdx.x * blockDim.x + threadIdx.x;
    int e4 = t * 4;
    if (e4 >= EE) return;
    int4 d = *(const int4*)&ei[EE + e4];
    atomicAdd(&g_cnt[d.x], 1);
    atomicAdd(&g_cnt[d.y], 1);
    atomicAdd(&g_cnt[d.z], 1);
    atomicAdd(&g_cnt[d.w], 1);
}

__device__ __forceinline__ int block_excl_scan(int v, int* warpsums) {
    int lane = threadIdx.x & 31, wid = threadIdx.x >> 5;
    int x = v;
#pragma unroll
    for (int off = 1; off < 32; off <<= 1) {
        int y = __shfl_up_sync(FULL, x, off);
        if (lane >= off) x += y;
    }
    if (lane == 31) warpsums[wid] = x;
    __syncthreads();
    if (wid == 0) {
        int nw = (blockDim.x + 31) >> 5;
        int s = (lane < nw) ? warpsums[lane] : 0;
#pragma unroll
        for (int off = 1; off < 32; off <<= 1) {
            int y = __shfl_up_sync(FULL, s, off);
            if (lane >= off) s += y;
        }
        warpsums[lane] = s;
    }
    __syncthreads();
    int base = (wid > 0) ? warpsums[wid - 1] : 0;
    return base + x - v;
}

// Single-kernel scan with spin-lookback. 49 blocks (all co-resident).
// g_part[b] published as (block_total + 1); 0 means not ready.
__global__ void k_scan() {
    __shared__ int ws[32];
    __shared__ int s_pre;
    int i = blockIdx.x * SCAN_T + threadIdx.x;
    int v = (i < NN) ? g_cnt[i] : 0;
    int ex = block_excl_scan(v, ws);
    if (threadIdx.x == SCAN_T - 1)
        atomicExch(&g_part[blockIdx.x], ex + v + 1);
    if (threadIdx.x < 32) {
        int acc = 0;
        for (int j = (int)threadIdx.x; j < (int)blockIdx.x; j += 32) {
            int p;
            do { p = atomicAdd(&g_part[j], 0); } while (p == 0);
            acc += p - 1;
        }
#pragma unroll
        for (int off = 16; off >= 1; off >>= 1)
            acc += __shfl_xor_sync(FULL, acc, off);
        if (threadIdx.x == 0) s_pre = acc;
    }
    __syncthreads();
    int r = ex + s_pre;
    if (i < NN) {
        g_rowstart[i] = r;
        g_cursor[i] = r;
        g_cnt[i] = 0;   // re-zero for next run
    }
    if (i == 0) g_rowstart[NN] = EE;
}

// Vectorized fill: 4 edges/thread (4 independent atomics in flight).
__global__ void k_fill(const int* __restrict__ ei) {
    int t = blockIdx.x * blockDim.x + threadIdx.x;
    int e4 = t * 4;
    if (e4 >= EE) return;
    int4 s = *(const int4*)&ei[e4];
    int4 d = *(const int4*)&ei[EE + e4];
    int p0 = atomicAdd(&g_cursor[d.x], 1);
    int p1 = atomicAdd(&g_cursor[d.y], 1);
    int p2 = atomicAdd(&g_cursor[d.z], 1);
    int p3 = atomicAdd(&g_cursor[d.w], 1);
    g_csr[p0] = s.x;
    g_csr[p1] = s.y;
    g_csr[p2] = s.z;
    g_csr[p3] = s.w;
}

// ---------------------------------------------------------------------------
__device__ __forceinline__ void acc_h(int s, int lane, float ex,
                                      float& a0, float& a1, float& a2, float& a3) {
    uint2 u = *(const uint2*)&g_hh[s * 64 + lane * 2];
    float2 f0 = __half22float2(*reinterpret_cast<__half2*>(&u.x));
    float2 f1 = __half22float2(*reinterpret_cast<__half2*>(&u.y));
    a0 += ex * f0.x; a1 += ex * f0.y; a2 += ex * f1.x; a3 += ex * f1.y;
}

__global__ void __launch_bounds__(256)
k_gather(const float* __restrict__ bias,
         const float* __restrict__ gamma,
         const float* __restrict__ beta,
         float* __restrict__ out) {
    int t = blockIdx.x * blockDim.x + threadIdx.x;
    int n = t >> 5, lane = t & 31;
    if (n >= NN) return;
    int head = lane >> 2;

    float adn = g_adst[n * HH + head];
    float a0 = 0.f, a1 = 0.f, a2 = 0.f, a3 = 0.f, den = 0.f;

    {   // self-loop
        float e = g_asrc[n * HH + head] + adn;
        e = e > 0.f ? e : NEG * e;
        float ex = __expf(e);
        acc_h(n, lane, ex, a0, a1, a2, a3);
        den += ex;
    }

    int start = g_rowstart[n], end = g_rowstart[n + 1];
    for (int base = start; base < end; base += 32) {
        int j = base + lane;
        int sj = (j < end) ? g_csr[j] : 0;
        int m = min(32, end - base);
        int k = 0;
        for (; k + 8 <= m; k += 8) {
            int s[8];
            float e[8], xx[8];
#pragma unroll
            for (int q = 0; q < 8; q++) s[q] = __shfl_sync(FULL, sj, k + q);
#pragma unroll
            for (int q = 0; q < 8; q++) e[q] = g_asrc[s[q] * HH + head] + adn;
#pragma unroll
            for (int q = 0; q < 8; q++) {
                e[q] = e[q] > 0.f ? e[q] : NEG * e[q];
                xx[q] = __expf(e[q]);
            }
#pragma unroll
            for (int q = 0; q < 8; q++) acc_h(s[q], lane, xx[q], a0, a1, a2, a3);
#pragma unroll
            for (int q = 0; q < 8; q++) den += xx[q];
        }
        for (; k + 4 <= m; k += 4) {
            int s[4];
            float e[4], xx[4];
#pragma unroll
            for (int q = 0; q < 4; q++) s[q] = __shfl_sync(FULL, sj, k + q);
#pragma unroll
            for (int q = 0; q < 4; q++) e[q] = g_asrc[s[q] * HH + head] + adn;
#pragma unroll
            for (int q = 0; q < 4; q++) {
                e[q] = e[q] > 0.f ? e[q] : NEG * e[q];
                xx[q] = __expf(e[q]);
            }
#pragma unroll
            for (int q = 0; q < 4; q++) acc_h(s[q], lane, xx[q], a0, a1, a2, a3);
#pragma unroll
            for (int q = 0; q < 4; q++) den += xx[q];
        }
        for (; k < m; k++) {
            int s = __shfl_sync(FULL, sj, k);
            float e = g_asrc[s * HH + head] + adn;
            e = e > 0.f ? e : NEG * e;
            float ex = __expf(e);
            acc_h(s, lane, ex, a0, a1, a2, a3);
            den += ex;
        }
    }

    float inv = 1.0f / den;
    uint2 us = *(const uint2*)&g_sk[n * 64 + lane * 2];
    float2 s0 = __half22float2(*reinterpret_cast<__half2*>(&us.x));
    float2 s1 = __half22float2(*reinterpret_cast<__half2*>(&us.y));
    float4 b  = *(const float4*)&bias[lane * 4];
    float z0 = a0 * inv + b.x + 0.1f * s0.x;
    float z1 = a1 * inv + b.y + 0.1f * s0.y;
    float z2 = a2 * inv + b.z + 0.1f * s1.x;
    float z3 = a3 * inv + b.w + 0.1f * s1.y;

    float sum = z0 + z1 + z2 + z3;
    float sq  = z0 * z0 + z1 * z1 + z2 * z2 + z3 * z3;
#pragma unroll
    for (int off = 16; off >= 1; off >>= 1) {
        sum += __shfl_xor_sync(FULL, sum, off);
        sq  += __shfl_xor_sync(FULL, sq, off);
    }
    float mu   = sum * (1.0f / 128.0f);
    float var  = sq * (1.0f / 128.0f) - mu * mu;
    float rstd = rsqrtf(var + 1e-5f);
    float4 g  = *(const float4*)&gamma[lane * 4];
    float4 be = *(const float4*)&beta[lane * 4];
    float y0 = (z0 - mu) * rstd * g.x + be.x;
    float y1 = (z1 - mu) * rstd * g.y + be.y;
    float y2 = (z2 - mu) * rstd * g.z + be.z;
    float y3 = (z3 - mu) * rstd * g.w + be.w;
    y0 = y0 > 0.f ? y0 : expm1f(y0);
    y1 = y1 > 0.f ? y1 : expm1f(y1);
    y2 = y2 > 0.f ? y2 : expm1f(y2);
    y3 = y3 > 0.f ? y3 : expm1f(y3);
    *(float4*)&out[n * HC + lane * 4] = make_float4(y0, y1, y2, y3);
}

// ---------------------------------------------------------------------------
extern "C" void kernel_launch(void* const* d_in, const int* in_sizes, int n_in,
                              void* d_out, int out_size) {
    const float* x       = (const float*)d_in[0];
    const int*   ei      = (const int*)d_in[1];
    const float* W_gat   = (const float*)d_in[2];
    const float* att_src = (const float*)d_in[3];
    const float* att_dst = (const float*)d_in[4];
    const float* bias    = (const float*)d_in[5];
    const float* W_skip  = (const float*)d_in[6];
    const float* gamma   = (const float*)d_in[7];
    const float* beta    = (const float*)d_in[8];
    float* out = (float*)d_out;

    static cudaStream_t s1 = nullptr;
    static cudaEvent_t evFork = nullptr, evPrep = nullptr, evJoin = nullptr;
    if (!s1) {
        cudaStreamCreateWithFlags(&s1, cudaStreamNonBlocking);
        cudaEventCreateWithFlags(&evFork, cudaEventDisableTiming);
        cudaEventCreateWithFlags(&evPrep, cudaEventDisableTiming);
        cudaEventCreateWithFlags(&evJoin, cudaEventDisableTiming);
        cudaFuncSetAttribute(k_mm, cudaFuncAttributeMaxDynamicSharedMemorySize, SMEM_MM);
        cudaFuncSetAttribute(k_mmskip, cudaFuncAttributeMaxDynamicSharedMemorySize, SMEM_MM);
    }

    // Fork: CSR build + skip GEMM on s1; prep + gat GEMM on main.
    cudaEventRecord(evFork, 0);
    cudaStreamWaitEvent(s1, evFork, 0);

    k_hist<<<(EE / 4 + 255) / 256, 256, 0, s1>>>(ei);
    k_scan<<<NB, SCAN_T, 0, s1>>>();
    k_fill<<<(EE / 4 + 255) / 256, 256, 0, s1>>>(ei);

    k_prep<<<XBLK + WBLK, 256>>>(x, W_gat, W_skip);
    cudaEventRecord(evPrep, 0);
    cudaStreamWaitEvent(s1, evPrep, 0);
    k_mmskip<<<(NN + 127) / 128, 256, SMEM_MM, s1>>>();
    cudaEventRecord(evJoin, s1);

    k_mm<<<(NN + 127) / 128, 256, SMEM_MM>>>(att_src, att_dst);

    // Join, then gather.
    cudaStreamWaitEvent(0, evJoin, 0);
    k_gather<<<(NN * 32 + 255) / 256, 256>>>(bias, gamma, beta, out);
}

// round 15
// speedup vs baseline: 1.0048x; 1.0048x over previous
#include <cuda_runtime.h>
#include <cuda_fp16.h>
#include <cuda_bf16.h>

#define NN 50000
#define EE 800000
#define HH 8
#define HC 128
#define NEG 0.2f
#define FULL 0xffffffffu

#define SCAN_T 1024
#define NB ((NN + SCAN_T - 1) / SCAN_T)   // 49

// Scratch (device globals; no cudaMalloc anywhere)
__device__ __nv_bfloat16 g_xs[NN * 256];   // [Xhi | Xlo] per row (bf16, gat GEMM)
__device__ __half        g_xh[NN * 128];   // X fp16 (skip GEMM)
__device__ __nv_bfloat16 g_wc[128 * 384];  // gat W^T: row n, k: [Whi | Wlo | Whi]
__device__ __half        g_wh[128 * 128];  // skip W^T fp16
__device__ __half2 g_hh[NN * 64];          // h  (fp16 messages)
__device__ __half2 g_sk[NN * 64];          // skip (fp16)
__device__ float   g_asrc[NN * HH];
__device__ float   g_adst[NN * HH];
__device__ int     g_cnt[NN];              // zero at run start (re-zeroed each run)
__device__ int     g_rowstart[NN + 1];
__device__ int     g_cursor[NN];
__device__ int     g_part[NB];             // scan partials+flag; zeroed in k_hist
__device__ int     g_csr[EE];

// ---------------------------------------------------------------------------
// Merged prep: X hi/lo split (bf16) + X fp16 + transposed weights (bf16 gat / fp16 skip).
#define XBLK ((NN * 32 + 255) / 256)
#define WBLK 96                            // 256*96 threads / 256

__global__ void k_prep(const float* __restrict__ X,
                       const float* __restrict__ Wg,
                       const float* __restrict__ Ws) {
    if (blockIdx.x < XBLK) {
        int t = blockIdx.x * 256 + threadIdx.x;
        int n = t >> 5, c4 = (t & 31) * 4;
        if (n >= NN) return;
        float4 v = *(const float4*)&X[n * 128 + c4];
        __nv_bfloat16 h0 = __float2bfloat16_rn(v.x);
        __nv_bfloat16 h1 = __float2bfloat16_rn(v.y);
        __nv_bfloat16 h2 = __float2bfloat16_rn(v.z);
        __nv_bfloat16 h3 = __float2bfloat16_rn(v.w);
        __nv_bfloat16 l0 = __float2bfloat16_rn(v.x - __bfloat162float(h0));
        __nv_bfloat16 l1 = __float2bfloat16_rn(v.y - __bfloat162float(h1));
        __nv_bfloat16 l2 = __float2bfloat16_rn(v.z - __bfloat162float(h2));
        __nv_bfloat16 l3 = __float2bfloat16_rn(v.w - __bfloat162float(h3));
        __nv_bfloat16 hi4[4] = {h0, h1, h2, h3};
        __nv_bfloat16 lo4[4] = {l0, l1, l2, l3};
        long base = (long)n * 256;
        *(uint2*)&g_xs[base + c4]       = *(uint2*)hi4;
        *(uint2*)&g_xs[base + 128 + c4] = *(uint2*)lo4;
        __half2 f01 = __floats2half2_rn(v.x, v.y);
        __half2 f23 = __floats2half2_rn(v.z, v.w);
        uint2 uf;
        uf.x = *(unsigned*)&f01; uf.y = *(unsigned*)&f23;
        *(uint2*)&g_xh[(long)n * 128 + c4] = uf;
    } else {
        int t = (blockIdx.x - XBLK) * 256 + threadIdx.x;   // 256*96 groups of 4
        if (t >= 256 * 96) return;
        int n = t / 96, kq = t % 96;
        int k0 = kq * 4;
        if (n < 128) {
            __nv_bfloat16 out4[4];
#pragma unroll
            for (int j = 0; j < 4; j++) {
                int k = k0 + j;
                int kk = k & 127;
                float w = Wg[kk * 128 + n];
                __nv_bfloat16 hi = __float2bfloat16_rn(w);
                out4[j] = (k >= 128 && k < 256)
                    ? __float2bfloat16_rn(w - __bfloat162float(hi)) : hi;
            }
            *(uint2*)&g_wc[n * 384 + k0] = *(uint2*)out4;
        } else if (k0 < 128) {
            int nn = n - 128;
            __half out4[4];
#pragma unroll
            for (int j = 0; j < 4; j++)
                out4[j] = __float2half_rn(Ws[(k0 + j) * 128 + nn]);
            *(uint2*)&g_wh[nn * 128 + k0] = *(uint2*)out4;
        }
    }
}

// ---------------------------------------------------------------------------
// Shared tensor-core GEMM plumbing.
#define KCH 32
#define LDA 40
#define ABUF (128 * LDA)
#define SMEM_MM (6 * ABUF * 2)           // 61440 bytes

__device__ __forceinline__ void ldsm_x4(unsigned& r0, unsigned& r1,
                                        unsigned& r2, unsigned& r3, unsigned addr) {
    asm volatile("ldmatrix.sync.aligned.m8n8.x4.shared.b16 {%0,%1,%2,%3}, [%4];"
                 : "=r"(r0), "=r"(r1), "=r"(r2), "=r"(r3) : "r"(addr));
}

// ---------------------------------------------------------------------------
// GAT GEMM (bf16 3-pass, virtual K=384), h + attention dots. Grid: 391 blocks.
#define NCH 12

__global__ void __launch_bounds__(256)
k_mm(const float* __restrict__ att_s, const float* __restrict__ att_d) {
    extern __shared__ __nv_bfloat16 smem[];
    int tid = threadIdx.x;
    int wid = tid >> 5, lane = tid & 31;
    int g = lane >> 2, t = lane & 3;
    int m0 = blockIdx.x * 128;
    int wrow = (wid >> 1) * 32, wcol = (wid & 1) * 64;

    unsigned s_base = (unsigned)__cvta_generic_to_shared(&smem[0]);
    const unsigned stage_bytes = ABUF * 2;

    int r0i = tid >> 2, c8 = (tid & 3) * 8;
    int r1i = (tid + 256) >> 2;
    int gmA0 = m0 + r0i, gmA1 = m0 + r1i;
    const __nv_bfloat16* wrow0 = &g_wc[r0i * 384 + c8];
    const __nv_bfloat16* wrow1 = &g_wc[r1i * 384 + c8];
    const __nv_bfloat16* xrow0 = &g_xs[(long)min(gmA0, NN - 1) * 256 + c8];
    const __nv_bfloat16* xrow1 = &g_xs[(long)min(gmA1, NN - 1) * 256 + c8];
    int szA0 = (gmA0 < NN) ? 16 : 0;
    int szA1 = (gmA1 < NN) ? 16 : 0;
    unsigned dA0 = s_base + (r0i * LDA + c8) * 2;
    unsigned dA1 = s_base + (r1i * LDA + c8) * 2;
    unsigned dB0 = s_base + 3 * stage_bytes + (r0i * LDA + c8) * 2;
    unsigned dB1 = s_base + 3 * stage_bytes + (r1i * LDA + c8) * 2;

#define PREFETCH(ch) do {                                                     \
        if ((ch) < NCH) {                                                     \
            int _ach = ((ch) < 4) ? (ch) : (ch) - 4;                          \
            int _ka = _ach * KCH, _kb = (ch) * KCH;                           \
            unsigned _o = ((ch) % 3) * stage_bytes;                           \
            asm volatile("cp.async.ca.shared.global [%0], [%1], 16, %2;"      \
                         :: "r"(dA0 + _o), "l"(xrow0 + _ka), "r"(szA0));      \
            asm volatile("cp.async.ca.shared.global [%0], [%1], 16, %2;"      \
                         :: "r"(dA1 + _o), "l"(xrow1 + _ka), "r"(szA1));      \
            asm volatile("cp.async.ca.shared.global [%0], [%1], 16;"          \
                         :: "r"(dB0 + _o), "l"(wrow0 + _kb));                 \
            asm volatile("cp.async.ca.shared.global [%0], [%1], 16;"          \
                         :: "r"(dB1 + _o), "l"(wrow1 + _kb));                 \
        }                                                                     \
        asm volatile("cp.async.commit_group;");                               \
    } while (0)

    float d[2][8][4];
#pragma unroll
    for (int mi = 0; mi < 2; mi++)
#pragma unroll
        for (int ni = 0; ni < 8; ni++)
#pragma unroll
            for (int j = 0; j < 4; j++) d[mi][ni][j] = 0.f;

    int a_row = (lane & 15), a_kof = (lane >> 4) * 8;
    int b_row = (lane & 7) + ((lane >> 4) << 3), b_kof = ((lane >> 3) & 1) * 8;

    PREFETCH(0);
    PREFETCH(1);

    for (int c = 0; c < NCH; c++) {
        asm volatile("cp.async.wait_group 1;");
        __syncthreads();
        PREFETCH(c + 2);
        unsigned abuf = s_base + (c % 3) * stage_bytes;
        unsigned bbuf = s_base + (3 + c % 3) * stage_bytes;
#pragma unroll
        for (int kk = 0; kk < KCH; kk += 16) {
            unsigned a[2][4], b[8][2];
#pragma unroll
            for (int mi = 0; mi < 2; mi++) {
                int rb = wrow + 16 * mi;
                unsigned ad = abuf + ((rb + a_row) * LDA + kk + a_kof) * 2;
                ldsm_x4(a[mi][0], a[mi][1], a[mi][2], a[mi][3], ad);
            }
#pragma unroll
            for (int bi = 0; bi < 4; bi++) {
                int nb = wcol + 16 * bi + b_row;
                unsigned bd = bbuf + (nb * LDA + kk + b_kof) * 2;
                ldsm_x4(b[2 * bi][0], b[2 * bi][1], b[2 * bi + 1][0], b[2 * bi + 1][1], bd);
            }
#pragma unroll
            for (int mi = 0; mi < 2; mi++)
#pragma unroll
                for (int ni = 0; ni < 8; ni++) {
                    asm volatile(
                        "mma.sync.aligned.m16n8k16.row.col.f32.bf16.bf16.f32 "
                        "{%0,%1,%2,%3}, {%4,%5,%6,%7}, {%8,%9}, {%0,%1,%2,%3};\n"
                        : "+f"(d[mi][ni][0]), "+f"(d[mi][ni][1]),
                          "+f"(d[mi][ni][2]), "+f"(d[mi][ni][3])
                        : "r"(a[mi][0]), "r"(a[mi][1]), "r"(a[mi][2]), "r"(a[mi][3]),
                          "r"(b[ni][0]), "r"(b[ni][1]));
                }
        }
    }

#pragma unroll
    for (int mi = 0; mi < 2; mi++) {
        int r0 = m0 + wrow + 16 * mi + g;
        int r1 = r0 + 8;
#pragma unroll
        for (int ni = 0; ni < 8; ni++) {
            int pidx = wcol / 2 + 4 * ni + t;
            if (r0 < NN) g_hh[r0 * 64 + pidx] = __floats2half2_rn(d[mi][ni][0], d[mi][ni][1]);
            if (r1 < NN) g_hh[r1 * 64 + pidx] = __floats2half2_rn(d[mi][ni][2], d[mi][ni][3]);
        }
#pragma unroll
        for (int lh = 0; lh < 4; lh++) {
            float ps0 = 0.f, pd0 = 0.f, ps1 = 0.f, pd1 = 0.f;
#pragma unroll
            for (int j = 0; j < 2; j++) {
                int ni = 2 * lh + j;
                int c0 = wcol + 8 * ni + 2 * t;
                float as0 = att_s[c0], as1 = att_s[c0 + 1];
                float ad0 = att_d[c0], ad1 = att_d[c0 + 1];
                ps0 += d[mi][ni][0] * as0 + d[mi][ni][1] * as1;
                pd0 += d[mi][ni][0] * ad0 + d[mi][ni][1] * ad1;
                ps1 += d[mi][ni][2] * as0 + d[mi][ni][3] * as1;
                pd1 += d[mi][ni][2] * ad0 + d[mi][ni][3] * ad1;
            }
            ps0 += __shfl_xor_sync(FULL, ps0, 1); ps0 += __shfl_xor_sync(FULL, ps0, 2);
            pd0 += __shfl_xor_sync(FULL, pd0, 1); pd0 += __shfl_xor_sync(FULL, pd0, 2);
            ps1 += __shfl_xor_sync(FULL, ps1, 1); ps1 += __shfl_xor_sync(FULL, ps1, 2);
            pd1 += __shfl_xor_sync(FULL, pd1, 1); pd1 += __shfl_xor_sync(FULL, pd1, 2);
            int head = wcol / 16 + lh;
            if (t == 0) {
                if (r0 < NN) { g_asrc[r0 * HH + head] = ps0; g_adst[r0 * HH + head] = pd0; }
                if (r1 < NN) { g_asrc[r1 * HH + head] = ps1; g_adst[r1 * HH + head] = pd1; }
            }
        }
    }
}

// ---------------------------------------------------------------------------
// SKIP GEMM: single fp16 pass, K=128 (4 chunks).
#define NCHS 4

__global__ void __launch_bounds__(256)
k_mmskip() {
    extern __shared__ __nv_bfloat16 smem[];
    int tid = threadIdx.x;
    int wid = tid >> 5, lane = tid & 31;
    int g = lane >> 2, t = lane & 3;
    int m0 = blockIdx.x * 128;
    int wrow = (wid >> 1) * 32, wcol = (wid & 1) * 64;

    unsigned s_base = (unsigned)__cvta_generic_to_shared(&smem[0]);
    const unsigned stage_bytes = ABUF * 2;

    int r0i = tid >> 2, c8 = (tid & 3) * 8;
    int r1i = (tid + 256) >> 2;
    int gmA0 = m0 + r0i, gmA1 = m0 + r1i;
    const __half* wrow0 = &g_wh[r0i * 128 + c8];
    const __half* wrow1 = &g_wh[r1i * 128 + c8];
    const __half* xrow0 = &g_xh[(long)min(gmA0, NN - 1) * 128 + c8];
    const __half* xrow1 = &g_xh[(long)min(gmA1, NN - 1) * 128 + c8];
    int szA0 = (gmA0 < NN) ? 16 : 0;
    int szA1 = (gmA1 < NN) ? 16 : 0;
    unsigned dA0 = s_base + (r0i * LDA + c8) * 2;
    unsigned dA1 = s_base + (r1i * LDA + c8) * 2;
    unsigned dB0 = s_base + 3 * stage_bytes + (r0i * LDA + c8) * 2;
    unsigned dB1 = s_base + 3 * stage_bytes + (r1i * LDA + c8) * 2;

#define PREFETCH_S(ch) do {                                                   \
        if ((ch) < NCHS) {                                                    \
            int _kb = (ch) * KCH;                                             \
            unsigned _o = ((ch) % 3) * stage_bytes;                           \
            asm volatile("cp.async.ca.shared.global [%0], [%1], 16, %2;"      \
                         :: "r"(dA0 + _o), "l"(xrow0 + _kb), "r"(szA0));      \
            asm volatile("cp.async.ca.shared.global [%0], [%1], 16, %2;"      \
                         :: "r"(dA1 + _o), "l"(xrow1 + _kb), "r"(szA1));      \
            asm volatile("cp.async.ca.shared.global [%0], [%1], 16;"          \
                         :: "r"(dB0 + _o), "l"(wrow0 + _kb));                 \
            asm volatile("cp.async.ca.shared.global [%0], [%1], 16;"          \
                         :: "r"(dB1 + _o), "l"(wrow1 + _kb));                 \
        }                                                                     \
        asm volatile("cp.async.commit_group;");                               \
    } while (0)

    float d[2][8][4];
#pragma unroll
    for (int mi = 0; mi < 2; mi++)
#pragma unroll
        for (int ni = 0; ni < 8; ni++)
#pragma unroll
            for (int j = 0; j < 4; j++) d[mi][ni][j] = 0.f;

    int a_row = (lane & 15), a_kof = (lane >> 4) * 8;
    int b_row = (lane & 7) + ((lane >> 4) << 3), b_kof = ((lane >> 3) & 1) * 8;

    PREFETCH_S(0);
    PREFETCH_S(1);

    for (int c = 0; c < NCHS; c++) {
        asm volatile("cp.async.wait_group 1;");
        __syncthreads();
        PREFETCH_S(c + 2);
        unsigned abuf = s_base + (c % 3) * stage_bytes;
        unsigned bbuf = s_base + (3 + c % 3) * stage_bytes;
#pragma unroll
        for (int kk = 0; kk < KCH; kk += 16) {
            unsigned a[2][4], b[8][2];
#pragma unroll
            for (int mi = 0; mi < 2; mi++) {
                int rb = wrow + 16 * mi;
                unsigned ad = abuf + ((rb + a_row) * LDA + kk + a_kof) * 2;
                ldsm_x4(a[mi][0], a[mi][1], a[mi][2], a[mi][3], ad);
            }
#pragma unroll
            for (int bi = 0; bi < 4; bi++) {
                int nb = wcol + 16 * bi + b_row;
                unsigned bd = bbuf + (nb * LDA + kk + b_kof) * 2;
                ldsm_x4(b[2 * bi][0], b[2 * bi][1], b[2 * bi + 1][0], b[2 * bi + 1][1], bd);
            }
#pragma unroll
            for (int mi = 0; mi < 2; mi++)
#pragma unroll
                for (int ni = 0; ni < 8; ni++) {
                    asm volatile(
                        "mma.sync.aligned.m16n8k16.row.col.f32.f16.f16.f32 "
                        "{%0,%1,%2,%3}, {%4,%5,%6,%7}, {%8,%9}, {%0,%1,%2,%3};\n"
                        : "+f"(d[mi][ni][0]), "+f"(d[mi][ni][1]),
                          "+f"(d[mi][ni][2]), "+f"(d[mi][ni][3])
                        : "r"(a[mi][0]), "r"(a[mi][1]), "r"(a[mi][2]), "r"(a[mi][3]),
                          "r"(b[ni][0]), "r"(b[ni][1]));
                }
        }
    }

#pragma unroll
    for (int mi = 0; mi < 2; mi++) {
        int r0 = m0 + wrow + 16 * mi + g;
        int r1 = r0 + 8;
#pragma unroll
        for (int ni = 0; ni < 8; ni++) {
            int pidx = wcol / 2 + 4 * ni + t;
            if (r0 < NN) g_sk[r0 * 64 + pidx] = __floats2half2_rn(d[mi][ni][0], d[mi][ni][1]);
            if (r1 < NN) g_sk[r1 * 64 + pidx] = __floats2half2_rn(d[mi][ni][2], d[mi][ni][3]);
        }
    }
}

// ---------------------------------------------------------------------------
// CSR build: vectorized histogram (4 edges/thread) + g_part flag-zeroing.
__global__ void k_hist(const int* __restrict__ ei) {
    if (blockIdx.x == 0 && threadIdx.x < NB) g_part[threadIdx.x] = 0;
    int t = blockIdx.x * blockDim.x + threadIdx.x;
    int e4 = t * 4;
    if (e4 >= EE) return;
    int4 d = *(const int4*)&ei[EE + e4];
    atomicAdd(&g_cnt[d.x], 1);
    atomicAdd(&g_cnt[d.y], 1);
    atomicAdd(&g_cnt[d.z], 1);
    atomicAdd(&g_cnt[d.w], 1);
}

__device__ __forceinline__ int block_excl_scan(int v, int* warpsums) {
    int lane = threadIdx.x & 31, wid = threadIdx.x >> 5;
    int x = v;
#pragma unroll
    for (int off = 1; off < 32; off <<= 1) {
        int y = __shfl_up_sync(FULL, x, off);
        if (lane >= off) x += y;
    }
    if (lane == 31) warpsums[wid] = x;
    __syncthreads();
    if (wid == 0) {
        int nw = (blockDim.x + 31) >> 5;
        int s = (lane < nw) ? warpsums[lane] : 0;
#pragma unroll
        for (int off = 1; off < 32; off <<= 1) {
            int y = __shfl_up_sync(FULL, s, off);
            if (lane >= off) s += y;
        }
        warpsums[lane] = s;
    }
    __syncthreads();
    int base = (wid > 0) ? warpsums[wid - 1] : 0;
    return base + x - v;
}

// Single-kernel scan with spin-lookback. 49 blocks (all co-resident).
__global__ void k_scan() {
    __shared__ int ws[32];
    __shared__ int s_pre;
    int i = blockIdx.x * SCAN_T + threadIdx.x;
    int v = (i < NN) ? g_cnt[i] : 0;
    int ex = block_excl_scan(v, ws);
    if (threadIdx.x == SCAN_T - 1)
        atomicExch(&g_part[blockIdx.x], ex + v + 1);
    if (threadIdx.x < 32) {
        int acc = 0;
        for (int j = (int)threadIdx.x; j < (int)blockIdx.x; j += 32) {
            int p;
            do { p = atomicAdd(&g_part[j], 0); } while (p == 0);
            acc += p - 1;
        }
#pragma unroll
        for (int off = 16; off >= 1; off >>= 1)
            acc += __shfl_xor_sync(FULL, acc, off);
        if (threadIdx.x == 0) s_pre = acc;
    }
    __syncthreads();
    int r = ex + s_pre;
    if (i < NN) {
        g_rowstart[i] = r;
        g_cursor[i] = r;
        g_cnt[i] = 0;   // re-zero for next run
    }
    if (i == 0) g_rowstart[NN] = EE;
}

// Vectorized fill: 4 edges/thread.
__global__ void k_fill(const int* __restrict__ ei) {
    int t = blockIdx.x * blockDim.x + threadIdx.x;
    int e4 = t * 4;
    if (e4 >= EE) return;
    int4 s = *(const int4*)&ei[e4];
    int4 d = *(const int4*)&ei[EE + e4];
    int p0 = atomicAdd(&g_cursor[d.x], 1);
    int p1 = atomicAdd(&g_cursor[d.y], 1);
    int p2 = atomicAdd(&g_cursor[d.z], 1);
    int p3 = atomicAdd(&g_cursor[d.w], 1);
    g_csr[p0] = s.x;
    g_csr[p1] = s.y;
    g_csr[p2] = s.z;
    g_csr[p3] = s.w;
}

// ---------------------------------------------------------------------------
__device__ __forceinline__ void acc_h(int s, int lane, float ex,
                                      float& a0, float& a1, float& a2, float& a3) {
    uint2 u = *(const uint2*)&g_hh[s * 64 + lane * 2];
    float2 f0 = __half22float2(*reinterpret_cast<__half2*>(&u.x));
    float2 f1 = __half22float2(*reinterpret_cast<__half2*>(&u.y));
    a0 += ex * f0.x; a1 += ex * f0.y; a2 += ex * f1.x; a3 += ex * f1.y;
}

// Gather: one warp per dst node. 4-edge groups: producer lanes (q=lane>>3,
// h=lane&7) compute exp-weights once per (edge, head); consumers shfl their
// head's weight. 1 LDG + 1 MUFU per 4 edges instead of 4 + 4.
__global__ void __launch_bounds__(256)
k_gather(const float* __restrict__ bias,
         const float* __restrict__ gamma,
         const float* __restrict__ beta,
         float* __restrict__ out) {
    int t = blockIdx.x * blockDim.x + threadIdx.x;
    int n = t >> 5, lane = t & 31;
    if (n >= NN) return;
    int head = lane >> 2;       // consumer head (lane covers 4 cols of it)
    int phead = lane & 7;       // producer head
    int pq = lane >> 3;         // producer edge-in-group

    float adn_c = g_adst[n * HH + head];
    float adn_p = g_adst[n * HH + phead];
    float a0 = 0.f, a1 = 0.f, a2 = 0.f, a3 = 0.f, den = 0.f;

    {   // self-loop
        float e = g_asrc[n * HH + head] + adn_c;
        e = e > 0.f ? e : NEG * e;
        float ex = __expf(e);
        acc_h(n, lane, ex, a0, a1, a2, a3);
        den += ex;
    }

    int start = g_rowstart[n], end = g_rowstart[n + 1];
    for (int base = start; base < end; base += 32) {
        int j = base + lane;
        int sj = (j < end) ? g_csr[j] : 0;
        int m = min(32, end - base);
        for (int k = 0; k < m; k += 4) {
            // producer: weight for edge (k+pq), head phead
            int sq = __shfl_sync(FULL, sj, k + pq);
            float ev = g_asrc[sq * HH + phead] + adn_p;
            ev = ev > 0.f ? ev : NEG * ev;
            float w = __expf(ev);
            // edge src ids
            int s0 = __shfl_sync(FULL, sj, k);
            int s1 = __shfl_sync(FULL, sj, k + 1);
            int s2 = __shfl_sync(FULL, sj, k + 2);
            int s3 = __shfl_sync(FULL, sj, k + 3);
            // consumer weights (my head, edges k..k+3)
            float w0 = __shfl_sync(FULL, w, head);
            float w1 = __shfl_sync(FULL, w, 8 + head);
            float w2 = __shfl_sync(FULL, w, 16 + head);
            float w3 = __shfl_sync(FULL, w, 24 + head);
            if (k + 1 >= m) w1 = 0.f;
            if (k + 2 >= m) w2 = 0.f;
            if (k + 3 >= m) w3 = 0.f;
            acc_h(s0, lane, w0, a0, a1, a2, a3);
            acc_h(s1, lane, w1, a0, a1, a2, a3);
            acc_h(s2, lane, w2, a0, a1, a2, a3);
            acc_h(s3, lane, w3, a0, a1, a2, a3);
            den += w0 + w1 + w2 + w3;
        }
    }

    float inv = 1.0f / den;
    uint2 us = *(const uint2*)&g_sk[n * 64 + lane * 2];
    float2 s0 = __half22float2(*reinterpret_cast<__half2*>(&us.x));
    float2 s1 = __half22float2(*reinterpret_cast<__half2*>(&us.y));
    float4 b  = *(const float4*)&bias[lane * 4];
    float z0 = a0 * inv + b.x + 0.1f * s0.x;
    float z1 = a1 * inv + b.y + 0.1f * s0.y;
    float z2 = a2 * inv + b.z + 0.1f * s1.x;
    float z3 = a3 * inv + b.w + 0.1f * s1.y;

    float sum = z0 + z1 + z2 + z3;
    float sq  = z0 * z0 + z1 * z1 + z2 * z2 + z3 * z3;
#pragma unroll
    for (int off = 16; off >= 1; off >>= 1) {
        sum += __shfl_xor_sync(FULL, sum, off);
        sq  += __shfl_xor_sync(FULL, sq, off);
    }
    float mu   = sum * (1.0f / 128.0f);
    float var  = sq * (1.0f / 128.0f) - mu * mu;
    float rstd = rsqrtf(var + 1e-5f);
    float4 g  = *(const float4*)&gamma[lane * 4];
    float4 be = *(const float4*)&beta[lane * 4];
    float y0 = (z0 - mu) * rstd * g.x + be.x;
    float y1 = (z1 - mu) * rstd * g.y + be.y;
    float y2 = (z2 - mu) * rstd * g.z + be.z;
    float y3 = (z3 - mu) * rstd * g.w + be.w;
    y0 = y0 > 0.f ? y0 : expm1f(y0);
    y1 = y1 > 0.f ? y1 : expm1f(y1);
    y2 = y2 > 0.f ? y2 : expm1f(y2);
    y3 = y3 > 0.f ? y3 : expm1f(y3);
    *(float4*)&out[n * HC + lane * 4] = make_float4(y0, y1, y2, y3);
}

// ---------------------------------------------------------------------------
extern "C" void kernel_launch(void* const* d_in, const int* in_sizes, int n_in,
                              void* d_out, int out_size) {
    const float* x       = (const float*)d_in[0];
    const int*   ei      = (const int*)d_in[1];
    const float* W_gat   = (const float*)d_in[2];
    const float* att_src = (const float*)d_in[3];
    const float* att_dst = (const float*)d_in[4];
    const float* bias    = (const float*)d_in[5];
    const float* W_skip  = (const float*)d_in[6];
    const float* gamma   = (const float*)d_in[7];
    const float* beta    = (const float*)d_in[8];
    float* out = (float*)d_out;

    static cudaStream_t s1 = nullptr;
    static cudaEvent_t evFork = nullptr, evPrep = nullptr, evJoin = nullptr;
    if (!s1) {
        cudaStreamCreateWithFlags(&s1, cudaStreamNonBlocking);
        cudaEventCreateWithFlags(&evFork, cudaEventDisableTiming);
        cudaEventCreateWithFlags(&evPrep, cudaEventDisableTiming);
        cudaEventCreateWithFlags(&evJoin, cudaEventDisableTiming);
        cudaFuncSetAttribute(k_mm, cudaFuncAttributeMaxDynamicSharedMemorySize, SMEM_MM);
        cudaFuncSetAttribute(k_mmskip, cudaFuncAttributeMaxDynamicSharedMemorySize, SMEM_MM);
    }

    // Fork: CSR build + skip GEMM on s1; prep + gat GEMM on main.
    cudaEventRecord(evFork, 0);
    cudaStreamWaitEvent(s1, evFork, 0);

    k_hist<<<(EE / 4 + 255) / 256, 256, 0, s1>>>(ei);
    k_scan<<<NB, SCAN_T, 0, s1>>>();
    k_fill<<<(EE / 4 + 255) / 256, 256, 0, s1>>>(ei);

    k_prep<<<XBLK + WBLK, 256>>>(x, W_gat, W_skip);
    cudaEventRecord(evPrep, 0);
    cudaStreamWaitEvent(s1, evPrep, 0);
    k_mmskip<<<(NN + 127) / 128, 256, SMEM_MM, s1>>>();
    cudaEventRecord(evJoin, s1);

    k_mm<<<(NN + 127) / 128, 256, SMEM_MM>>>(att_src, att_dst);

    // Join, then gather.
    cudaStreamWaitEvent(0, evJoin, 0);
    k_gather<<<(NN * 32 + 255) / 256, 256>>>(bias, gamma, beta, out);
}